// round 1
// baseline (speedup 1.0000x reference)
#include <cuda_runtime.h>

typedef unsigned long long u64;

#define NP 32768          // pixels = F*H*W = 2*128*128
#define SEQ 512           // window sequence length = F*16*16
#define NG 512            // head*window groups = 8*64

// ---------------- scratch (static __device__; no allocation APIs) ----------
__device__ float g_q [NG * SEQ * 64];          // [g][i][d]  64 MB
__device__ float g_k [NG * SEQ * 64];          // [g][j][d]  64 MB
__device__ float g_v [NG * SEQ * 64];          // [g][j][d]  64 MB
__device__ float g_s [NG * SEQ * SEQ];         // [g][i][j] 512 MB
__device__ float g_ow[NG * SEQ * 64];          // attn out, window layout
__device__ float g_op[512 * NP];               // attn out, pixel layout [ch][p]

// ---------------- packed fp32 helpers (Blackwell f32x2 pipe) ---------------
__device__ __forceinline__ u64 ffma2(u64 a, u64 b, u64 c) {
    u64 d;
    asm("fma.rn.f32x2 %0, %1, %2, %3;" : "=l"(d) : "l"(a), "l"(b), "l"(c));
    return d;
}
__device__ __forceinline__ float2 up2(u64 v) {
    float2 r;
    asm("mov.b64 {%0, %1}, %2;" : "=f"(r.x), "=f"(r.y) : "l"(v));
    return r;
}

// ============================================================================
// Kernel 1: QKV projection.  out[o][p] = sum_c W[o][c] * x[c][p]
// o in [0,1536): 0-511 -> Q (wq), 512-1023 -> K (wkv rows 0-511),
// 1024-1535 -> V (wkv rows 512-1023). Scatter into window layout [g][i][d].
// Block tile 64 p x 64 o, K chunks of 16. Thread micro 4p x 4o (p-pairs packed).
// ============================================================================
__global__ void __launch_bounds__(256) proj_kernel(
    const float* __restrict__ x,
    const float* __restrict__ wq,
    const float* __restrict__ wkv)
{
    __shared__ __align__(16) float Xs[16][64];     // [c][p]
    __shared__ __align__(16) float Wsd[16][132];   // [c][2*o] duplicated

    const int tid = threadIdx.x;
    const int tx = tid & 15, ty = tid >> 4;
    const int p0 = blockIdx.x * 64;
    const int o0 = blockIdx.y * 64;

    u64 acc[2][4] = {0ull,0ull,0ull,0ull,0ull,0ull,0ull,0ull};

    const int orow = tid >> 2;                 // 0..63
    const int o    = o0 + orow;
    const float* arow = (o < 512) ? (wq + o * 256) : (wkv + (o - 512) * 256);
    const int cg = (tid & 3) * 4;
    const int xr = tid >> 4;                   // 0..15
    const int xc = (tid & 15) * 4;

    for (int kt = 0; kt < 16; kt++) {
        const int c0 = kt * 16;
        *(float4*)&Xs[xr][xc] = *(const float4*)&x[(c0 + xr) * NP + p0 + xc];
        float4 w = *(const float4*)&arow[c0 + cg];
        *(float2*)&Wsd[cg + 0][2 * orow] = make_float2(w.x, w.x);
        *(float2*)&Wsd[cg + 1][2 * orow] = make_float2(w.y, w.y);
        *(float2*)&Wsd[cg + 2][2 * orow] = make_float2(w.z, w.z);
        *(float2*)&Wsd[cg + 3][2 * orow] = make_float2(w.w, w.w);
        __syncthreads();
        #pragma unroll
        for (int kk = 0; kk < 16; kk++) {
            ulonglong2 xp = *(const ulonglong2*)&Xs[kk][ty * 4];
            ulonglong2 wA = *(const ulonglong2*)&Wsd[kk][tx * 8];
            ulonglong2 wB = *(const ulonglong2*)&Wsd[kk][tx * 8 + 4];
            acc[0][0] = ffma2(xp.x, wA.x, acc[0][0]);
            acc[0][1] = ffma2(xp.x, wA.y, acc[0][1]);
            acc[0][2] = ffma2(xp.x, wB.x, acc[0][2]);
            acc[0][3] = ffma2(xp.x, wB.y, acc[0][3]);
            acc[1][0] = ffma2(xp.y, wA.x, acc[1][0]);
            acc[1][1] = ffma2(xp.y, wA.y, acc[1][1]);
            acc[1][2] = ffma2(xp.y, wB.x, acc[1][2]);
            acc[1][3] = ffma2(xp.y, wB.y, acc[1][3]);
        }
        __syncthreads();
    }

    // epilogue: scatter to window layout, float4 along d
    const int ob   = o0 + tx * 4;
    const int sel  = ob >> 9;
    const int oc   = ob & 511;
    const int head = oc >> 6;
    const int dl   = oc & 63;
    float* buf = (sel == 0) ? g_q : ((sel == 1) ? g_k : g_v);

    #pragma unroll
    for (int pe = 0; pe < 2; pe++) {
        float2 r0 = up2(acc[pe][0]);
        float2 r1 = up2(acc[pe][1]);
        float2 r2 = up2(acc[pe][2]);
        float2 r3 = up2(acc[pe][3]);
        #pragma unroll
        for (int h = 0; h < 2; h++) {
            int p   = p0 + ty * 4 + pe * 2 + h;
            int f   = p >> 14;
            int hh  = (p >> 7) & 127;
            int ww  = p & 127;
            int win = (hh >> 4) * 8 + (ww >> 4);
            int i   = f * 256 + (hh & 15) * 16 + (ww & 15);
            float4 v4;
            v4.x = h ? r0.y : r0.x;
            v4.y = h ? r1.y : r1.x;
            v4.z = h ? r2.y : r2.x;
            v4.w = h ? r3.y : r3.x;
            *(float4*)&buf[((head * 64 + win) * 512 + i) * 64 + dl] = v4;
        }
    }
}

// ============================================================================
// Kernel 2: S = scale * Q @ K^T per group.  Block tile 64 i x 64 j, d in 2x32.
// ============================================================================
__global__ void __launch_bounds__(256) qk_kernel()
{
    __shared__ __align__(16) float Qs [32][68];    // [d][i]
    __shared__ __align__(16) float Ksd[32][132];   // [d][2*j] duplicated

    const int tid = threadIdx.x;
    const int tx = tid & 15, ty = tid >> 4;
    const int g  = blockIdx.z;
    const int i0 = blockIdx.y * 64;
    const int j0 = blockIdx.x * 64;
    const float* qbase = g_q + g * SEQ * 64;
    const float* kbase = g_k + g * SEQ * 64;

    u64 acc[2][4] = {0ull,0ull,0ull,0ull,0ull,0ull,0ull,0ull};

    for (int dcb = 0; dcb < 2; dcb++) {
        const int dc = dcb * 32;
        #pragma unroll
        for (int q = 0; q < 2; q++) {
            int idx = q * 256 + tid;       // 0..511
            int row = idx >> 3;            // 0..63
            int dg  = (idx & 7) * 4;       // 0..28
            float4 qv = *(const float4*)&qbase[(i0 + row) * 64 + dc + dg];
            Qs[dg + 0][row] = qv.x;
            Qs[dg + 1][row] = qv.y;
            Qs[dg + 2][row] = qv.z;
            Qs[dg + 3][row] = qv.w;
            float4 kv = *(const float4*)&kbase[(j0 + row) * 64 + dc + dg];
            *(float2*)&Ksd[dg + 0][2 * row] = make_float2(kv.x, kv.x);
            *(float2*)&Ksd[dg + 1][2 * row] = make_float2(kv.y, kv.y);
            *(float2*)&Ksd[dg + 2][2 * row] = make_float2(kv.z, kv.z);
            *(float2*)&Ksd[dg + 3][2 * row] = make_float2(kv.w, kv.w);
        }
        __syncthreads();
        #pragma unroll
        for (int d = 0; d < 32; d++) {
            ulonglong2 qp = *(const ulonglong2*)&Qs[d][ty * 4];
            ulonglong2 kA = *(const ulonglong2*)&Ksd[d][tx * 8];
            ulonglong2 kB = *(const ulonglong2*)&Ksd[d][tx * 8 + 4];
            acc[0][0] = ffma2(qp.x, kA.x, acc[0][0]);
            acc[0][1] = ffma2(qp.x, kA.y, acc[0][1]);
            acc[0][2] = ffma2(qp.x, kB.x, acc[0][2]);
            acc[0][3] = ffma2(qp.x, kB.y, acc[0][3]);
            acc[1][0] = ffma2(qp.y, kA.x, acc[1][0]);
            acc[1][1] = ffma2(qp.y, kA.y, acc[1][1]);
            acc[1][2] = ffma2(qp.y, kB.x, acc[1][2]);
            acc[1][3] = ffma2(qp.y, kB.y, acc[1][3]);
        }
        __syncthreads();
    }

    const float scale = 0.125f;   // 64^-0.5
    #pragma unroll
    for (int pe = 0; pe < 2; pe++) {
        float2 r0 = up2(acc[pe][0]);
        float2 r1 = up2(acc[pe][1]);
        float2 r2 = up2(acc[pe][2]);
        float2 r3 = up2(acc[pe][3]);
        #pragma unroll
        for (int h = 0; h < 2; h++) {
            int i = i0 + ty * 4 + pe * 2 + h;
            float4 v4;
            v4.x = (h ? r0.y : r0.x) * scale;
            v4.y = (h ? r1.y : r1.x) * scale;
            v4.z = (h ? r2.y : r2.x) * scale;
            v4.w = (h ? r3.y : r3.x) * scale;
            *(float4*)&g_s[(g * 512 + i) * 512 + j0 + tx * 4] = v4;
        }
    }
}

// ============================================================================
// Kernel 3: row softmax over j (512). One warp per row, 16 values/lane.
// ============================================================================
__global__ void __launch_bounds__(256) softmax_kernel()
{
    const int warp = threadIdx.x >> 5;
    const int lane = threadIdx.x & 31;
    const long long row = (long long)blockIdx.x * 8 + warp;
    float* rp = g_s + row * 512;

    float4 v[4];
    #pragma unroll
    for (int c = 0; c < 4; c++) v[c] = *(const float4*)&rp[c * 128 + lane * 4];

    float m = -1e30f;
    #pragma unroll
    for (int c = 0; c < 4; c++)
        m = fmaxf(m, fmaxf(fmaxf(v[c].x, v[c].y), fmaxf(v[c].z, v[c].w)));
    #pragma unroll
    for (int s = 16; s > 0; s >>= 1)
        m = fmaxf(m, __shfl_xor_sync(0xffffffffu, m, s));

    float sum = 0.f;
    #pragma unroll
    for (int c = 0; c < 4; c++) {
        v[c].x = expf(v[c].x - m); v[c].y = expf(v[c].y - m);
        v[c].z = expf(v[c].z - m); v[c].w = expf(v[c].w - m);
        sum += v[c].x + v[c].y + v[c].z + v[c].w;
    }
    #pragma unroll
    for (int s = 16; s > 0; s >>= 1)
        sum += __shfl_xor_sync(0xffffffffu, sum, s);

    const float inv = 1.0f / sum;
    #pragma unroll
    for (int c = 0; c < 4; c++) {
        v[c].x *= inv; v[c].y *= inv; v[c].z *= inv; v[c].w *= inv;
        *(float4*)&rp[c * 128 + lane * 4] = v[c];
    }
}

// ============================================================================
// Kernel 4: O = P @ V per group.  Block tile 64 i x 64 d, j chunks of 16.
// Output in window layout g_ow[g][i][d].
// ============================================================================
__global__ void __launch_bounds__(256) pv_kernel()
{
    __shared__ __align__(16) float Ps [16][68];    // [j][i]
    __shared__ __align__(16) float Vsd[16][132];   // [j][2*d] duplicated

    const int tid = threadIdx.x;
    const int tx = tid & 15, ty = tid >> 4;
    const int g  = blockIdx.y;
    const int i0 = blockIdx.x * 64;
    const float* sbase = g_s + (long long)g * 512 * 512;
    const float* vbase = g_v + g * SEQ * 64;

    u64 acc[2][4] = {0ull,0ull,0ull,0ull,0ull,0ull,0ull,0ull};

    const int prow = tid >> 2;          // 0..63 (i)
    const int pjg  = (tid & 3) * 4;
    const int vrow = tid >> 4;          // 0..15 (j)
    const int vd4  = (tid & 15) * 4;

    for (int jt = 0; jt < 32; jt++) {
        const int j0 = jt * 16;
        float4 pv = *(const float4*)&sbase[(i0 + prow) * 512 + j0 + pjg];
        Ps[pjg + 0][prow] = pv.x;
        Ps[pjg + 1][prow] = pv.y;
        Ps[pjg + 2][prow] = pv.z;
        Ps[pjg + 3][prow] = pv.w;
        float4 vv = *(const float4*)&vbase[(j0 + vrow) * 64 + vd4];
        *(float2*)&Vsd[vrow][2 * (vd4 + 0)] = make_float2(vv.x, vv.x);
        *(float2*)&Vsd[vrow][2 * (vd4 + 1)] = make_float2(vv.y, vv.y);
        *(float2*)&Vsd[vrow][2 * (vd4 + 2)] = make_float2(vv.z, vv.z);
        *(float2*)&Vsd[vrow][2 * (vd4 + 3)] = make_float2(vv.w, vv.w);
        __syncthreads();
        #pragma unroll
        for (int jj = 0; jj < 16; jj++) {
            ulonglong2 pp = *(const ulonglong2*)&Ps[jj][ty * 4];
            ulonglong2 vA = *(const ulonglong2*)&Vsd[jj][tx * 8];
            ulonglong2 vB = *(const ulonglong2*)&Vsd[jj][tx * 8 + 4];
            acc[0][0] = ffma2(pp.x, vA.x, acc[0][0]);
            acc[0][1] = ffma2(pp.x, vA.y, acc[0][1]);
            acc[0][2] = ffma2(pp.x, vB.x, acc[0][2]);
            acc[0][3] = ffma2(pp.x, vB.y, acc[0][3]);
            acc[1][0] = ffma2(pp.y, vA.x, acc[1][0]);
            acc[1][1] = ffma2(pp.y, vA.y, acc[1][1]);
            acc[1][2] = ffma2(pp.y, vB.x, acc[1][2]);
            acc[1][3] = ffma2(pp.y, vB.y, acc[1][3]);
        }
        __syncthreads();
    }

    #pragma unroll
    for (int pe = 0; pe < 2; pe++) {
        float2 r0 = up2(acc[pe][0]);
        float2 r1 = up2(acc[pe][1]);
        float2 r2 = up2(acc[pe][2]);
        float2 r3 = up2(acc[pe][3]);
        #pragma unroll
        for (int h = 0; h < 2; h++) {
            int i = i0 + ty * 4 + pe * 2 + h;
            float4 v4;
            v4.x = h ? r0.y : r0.x;
            v4.y = h ? r1.y : r1.x;
            v4.z = h ? r2.y : r2.x;
            v4.w = h ? r3.y : r3.x;
            *(float4*)&g_ow[(g * 512 + i) * 64 + tx * 4] = v4;
        }
    }
}

// ============================================================================
// Kernel 5: window layout [g][i][d] -> pixel layout [ch][p] via SMEM staging.
// Tile: 128 i (8 full w2-runs) x 64 d. Reads and writes stay >=64B granular.
// ============================================================================
__global__ void __launch_bounds__(256) transpose_kernel()
{
    __shared__ __align__(16) float T[128][68];

    const int tid = threadIdx.x;
    const int g  = blockIdx.y;
    const int i0 = blockIdx.x * 128;
    const float* src = g_ow + (g * 512 + i0) * 64;

    #pragma unroll
    for (int q = 0; q < 8; q++) {
        int idx = q * 256 + tid;       // 0..2047
        int row = idx >> 4;            // 0..127
        int d4  = (idx & 15) * 4;
        *(float4*)&T[row][d4] = *(const float4*)&src[row * 64 + d4];
    }
    __syncthreads();

    const int head = g >> 6;
    const int win  = g & 63;
    const int wxv  = win >> 3, wyv = win & 7;

    #pragma unroll
    for (int q = 0; q < 2; q++) {
        int t   = q * 256 + tid;       // 0..511
        int d   = t & 63;
        int run = t >> 6;              // 0..7
        int ib  = run * 16;
        int ig  = i0 + ib;
        int f   = ig >> 8;
        int w1  = (ig >> 4) & 15;
        int pbase = f * 16384 + (wxv * 16 + w1) * 128 + wyv * 16;
        float* dst = g_op + (head * 64 + d) * NP + pbase;
        #pragma unroll
        for (int e = 0; e < 4; e++) {
            float4 v4;
            v4.x = T[ib + e * 4 + 0][d];
            v4.y = T[ib + e * 4 + 1][d];
            v4.z = T[ib + e * 4 + 2][d];
            v4.w = T[ib + e * 4 + 3][d];
            *(float4*)&dst[e * 4] = v4;
        }
    }
}

// ============================================================================
// Kernel 6: final projection + bias.  out[o][p] = sum_ic wo[o][ic]*g_op[ic][p]+bo
// Block tile 64 p x 64 o, K = 512 in chunks of 16.  Stores coalesced along p.
// ============================================================================
__global__ void __launch_bounds__(256) out_kernel(
    const float* __restrict__ wo,
    const float* __restrict__ bo,
    float* __restrict__ out)
{
    __shared__ __align__(16) float Bs[16][64];
    __shared__ __align__(16) float Wsd[16][132];

    const int tid = threadIdx.x;
    const int tx = tid & 15, ty = tid >> 4;
    const int p0 = blockIdx.x * 64;
    const int o0 = blockIdx.y * 64;

    u64 acc[2][4] = {0ull,0ull,0ull,0ull,0ull,0ull,0ull,0ull};

    const int xr = tid >> 4;
    const int xc = (tid & 15) * 4;
    const int orow = tid >> 2;
    const float* arow = wo + (o0 + orow) * 512;
    const int cg = (tid & 3) * 4;

    for (int kt = 0; kt < 32; kt++) {
        const int c0 = kt * 16;
        *(float4*)&Bs[xr][xc] = *(const float4*)&g_op[(c0 + xr) * NP + p0 + xc];
        float4 w = *(const float4*)&arow[c0 + cg];
        *(float2*)&Wsd[cg + 0][2 * orow] = make_float2(w.x, w.x);
        *(float2*)&Wsd[cg + 1][2 * orow] = make_float2(w.y, w.y);
        *(float2*)&Wsd[cg + 2][2 * orow] = make_float2(w.z, w.z);
        *(float2*)&Wsd[cg + 3][2 * orow] = make_float2(w.w, w.w);
        __syncthreads();
        #pragma unroll
        for (int kk = 0; kk < 16; kk++) {
            ulonglong2 xp = *(const ulonglong2*)&Bs[kk][tx * 4];
            ulonglong2 wA = *(const ulonglong2*)&Wsd[kk][ty * 8];
            ulonglong2 wB = *(const ulonglong2*)&Wsd[kk][ty * 8 + 4];
            acc[0][0] = ffma2(xp.x, wA.x, acc[0][0]);
            acc[0][1] = ffma2(xp.x, wA.y, acc[0][1]);
            acc[0][2] = ffma2(xp.x, wB.x, acc[0][2]);
            acc[0][3] = ffma2(xp.x, wB.y, acc[0][3]);
            acc[1][0] = ffma2(xp.y, wA.x, acc[1][0]);
            acc[1][1] = ffma2(xp.y, wA.y, acc[1][1]);
            acc[1][2] = ffma2(xp.y, wB.x, acc[1][2]);
            acc[1][3] = ffma2(xp.y, wB.y, acc[1][3]);
        }
        __syncthreads();
    }

    #pragma unroll
    for (int oo = 0; oo < 4; oo++) {
        int o_ = o0 + ty * 4 + oo;
        float b = bo[o_];
        float2 ra = up2(acc[0][oo]);
        float2 rb = up2(acc[1][oo]);
        float4 v4 = make_float4(ra.x + b, ra.y + b, rb.x + b, rb.y + b);
        *(float4*)&out[o_ * NP + p0 + tx * 4] = v4;
    }
}

// ============================================================================
extern "C" void kernel_launch(void* const* d_in, const int* in_sizes, int n_in,
                              void* d_out, int out_size)
{
    const float* x   = (const float*)d_in[0];
    const float* wq  = (const float*)d_in[1];
    const float* wkv = (const float*)d_in[2];
    const float* wo  = (const float*)d_in[3];
    const float* bo  = (const float*)d_in[4];
    float* out = (float*)d_out;

    proj_kernel     <<<dim3(NP / 64, 1536 / 64), 256>>>(x, wq, wkv);
    qk_kernel       <<<dim3(8, 8, NG),           256>>>();
    softmax_kernel  <<<dim3(NG * SEQ / 8),       256>>>();
    pv_kernel       <<<dim3(8, NG),              256>>>();
    transpose_kernel<<<dim3(4, NG),              256>>>();
    out_kernel      <<<dim3(NP / 64, 256 / 64),  256>>>(wo, bo, out);
}

// round 2
// speedup vs baseline: 2.4262x; 2.4262x over previous
#include <cuda_runtime.h>

typedef unsigned long long u64;

#define NP 32768          // pixels = F*H*W = 2*128*128
#define SEQ 512           // window sequence length = F*16*16
#define NG 512            // head*window groups = 8*64

// ---------------- scratch (static __device__; no allocation APIs) ----------
__device__ float g_q [NG * SEQ * 64];          // [g][i][d]  64 MB
__device__ float g_k [NG * SEQ * 64];          // [g][j][d]  64 MB
__device__ float g_v [NG * SEQ * 64];          // [g][j][d]  64 MB
__device__ float g_s [NG * SEQ * SEQ];         // [g][i][j] 512 MB
__device__ float g_ow[NG * SEQ * 64];          // attn out, window layout
__device__ float g_op[512 * NP];               // attn out, pixel layout [ch][p]

// ---------------- packed fp32 helpers (Blackwell f32x2 pipe) ---------------
__device__ __forceinline__ u64 ffma2(u64 a, u64 b, u64 c) {
    u64 d;
    asm("fma.rn.f32x2 %0, %1, %2, %3;" : "=l"(d) : "l"(a), "l"(b), "l"(c));
    return d;
}
__device__ __forceinline__ float2 up2(u64 v) {
    float2 r;
    asm("mov.b64 {%0, %1}, %2;" : "=f"(r.x), "=f"(r.y) : "l"(v));
    return r;
}
__device__ __forceinline__ u64 dup2(float v) {
    u64 d;
    asm("mov.b64 %0, {%1, %1};" : "=l"(d) : "f"(v));
    return d;
}

// 8x8 micro-tile inner step: A = 4 packed pairs, W = 8 floats (dup'd to pairs)
#define MICRO_STEP(XsRow, WsRow)                                              \
    {                                                                         \
        ulonglong2 a0 = *(const ulonglong2*)&(XsRow)[ty * 8];                 \
        ulonglong2 a1 = *(const ulonglong2*)&(XsRow)[ty * 8 + 4];             \
        float4 w0 = *(const float4*)&(WsRow)[tx * 8];                         \
        float4 w1 = *(const float4*)&(WsRow)[tx * 8 + 4];                     \
        u64 A[4] = {a0.x, a0.y, a1.x, a1.y};                                  \
        u64 Wv[8] = {dup2(w0.x), dup2(w0.y), dup2(w0.z), dup2(w0.w),          \
                     dup2(w1.x), dup2(w1.y), dup2(w1.z), dup2(w1.w)};         \
        _Pragma("unroll")                                                     \
        for (int pp = 0; pp < 4; pp++) {                                      \
            _Pragma("unroll")                                                 \
            for (int oo = 0; oo < 8; oo++)                                    \
                acc[pp][oo] = ffma2(A[pp], Wv[oo], acc[pp][oo]);              \
        }                                                                     \
    }

// ============================================================================
// Kernel 1: QKV projection. out[o][p] = sum_c W[o][c] * x[c][p]
// Block 128p x 128o, K chunks of 16, 256 threads, micro 8x8.
// Scatter into window layout [g][i][d].
// ============================================================================
__global__ void __launch_bounds__(256) proj_kernel(
    const float* __restrict__ x,
    const float* __restrict__ wq,
    const float* __restrict__ wkv)
{
    __shared__ __align__(16) float Xs[16][132];   // [c][p]
    __shared__ __align__(16) float Ws[16][132];   // [c][o]

    const int tid = threadIdx.x;
    const int tx = tid & 15, ty = tid >> 4;
    const int p0 = blockIdx.x * 128;
    const int o0 = blockIdx.y * 128;

    u64 acc[4][8];
    #pragma unroll
    for (int a = 0; a < 4; a++)
        #pragma unroll
        for (int b = 0; b < 8; b++) acc[a][b] = 0ull;

    for (int kt = 0; kt < 16; kt++) {
        const int c0 = kt * 16;
        #pragma unroll
        for (int q = 0; q < 2; q++) {
            int idx = q * 256 + tid;              // 0..511
            // X: 16 rows x 128 cols, direct copy
            int xr = idx >> 5;                    // 0..15
            int xc = (idx & 31) * 4;
            *(float4*)&Xs[xr][xc] = *(const float4*)&x[(c0 + xr) * NP + p0 + xc];
            // W: transpose load, float4 along c
            int orow = idx >> 2;                  // 0..127
            int cg   = (idx & 3) * 4;
            int o    = o0 + orow;
            const float* arow = (o < 512) ? (wq + o * 256) : (wkv + (o - 512) * 256);
            float4 w = *(const float4*)&arow[c0 + cg];
            Ws[cg + 0][orow] = w.x;
            Ws[cg + 1][orow] = w.y;
            Ws[cg + 2][orow] = w.z;
            Ws[cg + 3][orow] = w.w;
        }
        __syncthreads();
        #pragma unroll
        for (int kk = 0; kk < 16; kk++) MICRO_STEP(Xs[kk], Ws[kk]);
        __syncthreads();
    }

    // epilogue: scatter to window layout, two float4 along d per (p)
    const int ob   = o0 + tx * 8;
    const int sel  = ob >> 9;
    const int oc   = ob & 511;
    const int head = oc >> 6;
    const int dl   = oc & 63;
    float* buf = (sel == 0) ? g_q : ((sel == 1) ? g_k : g_v);

    #pragma unroll
    for (int pp = 0; pp < 4; pp++) {
        float2 r[8];
        #pragma unroll
        for (int oo = 0; oo < 8; oo++) r[oo] = up2(acc[pp][oo]);
        #pragma unroll
        for (int h = 0; h < 2; h++) {
            int p   = p0 + ty * 8 + pp * 2 + h;
            int f   = p >> 14;
            int hh  = (p >> 7) & 127;
            int ww  = p & 127;
            int win = (hh >> 4) * 8 + (ww >> 4);
            int i   = f * 256 + (hh & 15) * 16 + (ww & 15);
            float4 v0, v1;
            v0.x = h ? r[0].y : r[0].x;  v0.y = h ? r[1].y : r[1].x;
            v0.z = h ? r[2].y : r[2].x;  v0.w = h ? r[3].y : r[3].x;
            v1.x = h ? r[4].y : r[4].x;  v1.y = h ? r[5].y : r[5].x;
            v1.z = h ? r[6].y : r[6].x;  v1.w = h ? r[7].y : r[7].x;
            float* dst = &buf[((head * 64 + win) * 512 + i) * 64 + dl];
            *(float4*)&dst[0] = v0;
            *(float4*)&dst[4] = v1;
        }
    }
}

// ============================================================================
// Kernel 2: S = scale * Q @ K^T per group. Block 128i x 128j, 256 threads.
// ============================================================================
__global__ void __launch_bounds__(256) qk_kernel()
{
    __shared__ __align__(16) float Qs[16][132];   // [d][i]
    __shared__ __align__(16) float Ks[16][132];   // [d][j]

    const int tid = threadIdx.x;
    const int tx = tid & 15, ty = tid >> 4;
    const int g  = blockIdx.z;
    const int i0 = blockIdx.y * 128;
    const int j0 = blockIdx.x * 128;
    const float* qbase = g_q + g * SEQ * 64;
    const float* kbase = g_k + g * SEQ * 64;

    u64 acc[4][8];
    #pragma unroll
    for (int a = 0; a < 4; a++)
        #pragma unroll
        for (int b = 0; b < 8; b++) acc[a][b] = 0ull;

    for (int dcb = 0; dcb < 4; dcb++) {
        const int dc = dcb * 16;
        #pragma unroll
        for (int q = 0; q < 2; q++) {
            int idx = q * 256 + tid;              // 0..511
            int row = idx >> 2;                   // 0..127
            int dg  = (idx & 3) * 4;
            float4 qv = *(const float4*)&qbase[(i0 + row) * 64 + dc + dg];
            Qs[dg + 0][row] = qv.x;
            Qs[dg + 1][row] = qv.y;
            Qs[dg + 2][row] = qv.z;
            Qs[dg + 3][row] = qv.w;
            float4 kv = *(const float4*)&kbase[(j0 + row) * 64 + dc + dg];
            Ks[dg + 0][row] = kv.x;
            Ks[dg + 1][row] = kv.y;
            Ks[dg + 2][row] = kv.z;
            Ks[dg + 3][row] = kv.w;
        }
        __syncthreads();
        #pragma unroll
        for (int kk = 0; kk < 16; kk++) MICRO_STEP(Qs[kk], Ks[kk]);
        __syncthreads();
    }

    const float scale = 0.125f;   // 64^-0.5
    #pragma unroll
    for (int pp = 0; pp < 4; pp++) {
        float2 r[8];
        #pragma unroll
        for (int oo = 0; oo < 8; oo++) r[oo] = up2(acc[pp][oo]);
        #pragma unroll
        for (int h = 0; h < 2; h++) {
            int i = i0 + ty * 8 + pp * 2 + h;
            float4 v0, v1;
            v0.x = (h ? r[0].y : r[0].x) * scale;  v0.y = (h ? r[1].y : r[1].x) * scale;
            v0.z = (h ? r[2].y : r[2].x) * scale;  v0.w = (h ? r[3].y : r[3].x) * scale;
            v1.x = (h ? r[4].y : r[4].x) * scale;  v1.y = (h ? r[5].y : r[5].x) * scale;
            v1.z = (h ? r[6].y : r[6].x) * scale;  v1.w = (h ? r[7].y : r[7].x) * scale;
            float* dst = &g_s[(g * 512 + i) * 512 + j0 + tx * 8];
            *(float4*)&dst[0] = v0;
            *(float4*)&dst[4] = v1;
        }
    }
}

// ============================================================================
// Kernel 3: row softmax over j (512). One warp per row, 16 values/lane.
// ============================================================================
__global__ void __launch_bounds__(256) softmax_kernel()
{
    const int warp = threadIdx.x >> 5;
    const int lane = threadIdx.x & 31;
    const long long row = (long long)blockIdx.x * 8 + warp;
    float* rp = g_s + row * 512;

    float4 v[4];
    #pragma unroll
    for (int c = 0; c < 4; c++) v[c] = *(const float4*)&rp[c * 128 + lane * 4];

    float m = -1e30f;
    #pragma unroll
    for (int c = 0; c < 4; c++)
        m = fmaxf(m, fmaxf(fmaxf(v[c].x, v[c].y), fmaxf(v[c].z, v[c].w)));
    #pragma unroll
    for (int s = 16; s > 0; s >>= 1)
        m = fmaxf(m, __shfl_xor_sync(0xffffffffu, m, s));

    float sum = 0.f;
    #pragma unroll
    for (int c = 0; c < 4; c++) {
        v[c].x = __expf(v[c].x - m); v[c].y = __expf(v[c].y - m);
        v[c].z = __expf(v[c].z - m); v[c].w = __expf(v[c].w - m);
        sum += v[c].x + v[c].y + v[c].z + v[c].w;
    }
    #pragma unroll
    for (int s = 16; s > 0; s >>= 1)
        sum += __shfl_xor_sync(0xffffffffu, sum, s);

    const float inv = 1.0f / sum;
    #pragma unroll
    for (int c = 0; c < 4; c++) {
        v[c].x *= inv; v[c].y *= inv; v[c].z *= inv; v[c].w *= inv;
        *(float4*)&rp[c * 128 + lane * 4] = v[c];
    }
}

// ============================================================================
// Kernel 4: O = P @ V per group. Block 128i x 64d, 128 threads, micro 8x8.
// ============================================================================
__global__ void __launch_bounds__(128) pv_kernel()
{
    __shared__ __align__(16) float Ps[16][132];   // [j][i]
    __shared__ __align__(16) float Vs[16][68];    // [j][d]

    const int tid = threadIdx.x;
    const int tx = tid & 7, ty = tid >> 3;        // tx: 8 d-groups, ty: 16 i-groups
    const int g  = blockIdx.y;
    const int i0 = blockIdx.x * 128;
    const float* sbase = g_s + (long long)g * 512 * 512;
    const float* vbase = g_v + g * SEQ * 64;

    u64 acc[4][8];
    #pragma unroll
    for (int a = 0; a < 4; a++)
        #pragma unroll
        for (int b = 0; b < 8; b++) acc[a][b] = 0ull;

    for (int jt = 0; jt < 32; jt++) {
        const int j0 = jt * 16;
        #pragma unroll
        for (int q = 0; q < 4; q++) {
            int idx = q * 128 + tid;              // 0..511
            int row = idx >> 2;                   // 0..127 (i)
            int jg  = (idx & 3) * 4;
            float4 pv4 = *(const float4*)&sbase[(i0 + row) * 512 + j0 + jg];
            Ps[jg + 0][row] = pv4.x;
            Ps[jg + 1][row] = pv4.y;
            Ps[jg + 2][row] = pv4.z;
            Ps[jg + 3][row] = pv4.w;
        }
        #pragma unroll
        for (int q = 0; q < 2; q++) {
            int idx = q * 128 + tid;              // 0..255
            int row = idx >> 4;                   // 0..15 (j)
            int d4  = (idx & 15) * 4;
            *(float4*)&Vs[row][d4] = *(const float4*)&vbase[(j0 + row) * 64 + d4];
        }
        __syncthreads();
        #pragma unroll
        for (int kk = 0; kk < 16; kk++) MICRO_STEP(Ps[kk], Vs[kk]);
        __syncthreads();
    }

    #pragma unroll
    for (int pp = 0; pp < 4; pp++) {
        float2 r[8];
        #pragma unroll
        for (int oo = 0; oo < 8; oo++) r[oo] = up2(acc[pp][oo]);
        #pragma unroll
        for (int h = 0; h < 2; h++) {
            int i = i0 + ty * 8 + pp * 2 + h;
            float4 v0, v1;
            v0.x = h ? r[0].y : r[0].x;  v0.y = h ? r[1].y : r[1].x;
            v0.z = h ? r[2].y : r[2].x;  v0.w = h ? r[3].y : r[3].x;
            v1.x = h ? r[4].y : r[4].x;  v1.y = h ? r[5].y : r[5].x;
            v1.z = h ? r[6].y : r[6].x;  v1.w = h ? r[7].y : r[7].x;
            float* dst = &g_ow[(g * 512 + i) * 64 + tx * 8];
            *(float4*)&dst[0] = v0;
            *(float4*)&dst[4] = v1;
        }
    }
}

// ============================================================================
// Kernel 5: window layout [g][i][d] -> pixel layout [ch][p] via SMEM staging.
// ============================================================================
__global__ void __launch_bounds__(256) transpose_kernel()
{
    __shared__ __align__(16) float T[128][68];

    const int tid = threadIdx.x;
    const int g  = blockIdx.y;
    const int i0 = blockIdx.x * 128;
    const float* src = g_ow + (g * 512 + i0) * 64;

    #pragma unroll
    for (int q = 0; q < 8; q++) {
        int idx = q * 256 + tid;       // 0..2047
        int row = idx >> 4;            // 0..127
        int d4  = (idx & 15) * 4;
        *(float4*)&T[row][d4] = *(const float4*)&src[row * 64 + d4];
    }
    __syncthreads();

    const int head = g >> 6;
    const int win  = g & 63;
    const int wxv  = win >> 3, wyv = win & 7;

    #pragma unroll
    for (int q = 0; q < 2; q++) {
        int t   = q * 256 + tid;       // 0..511
        int d   = t & 63;
        int run = t >> 6;              // 0..7
        int ib  = run * 16;
        int ig  = i0 + ib;
        int f   = ig >> 8;
        int w1  = (ig >> 4) & 15;
        int pbase = f * 16384 + (wxv * 16 + w1) * 128 + wyv * 16;
        float* dst = g_op + (head * 64 + d) * NP + pbase;
        #pragma unroll
        for (int e = 0; e < 4; e++) {
            float4 v4;
            v4.x = T[ib + e * 4 + 0][d];
            v4.y = T[ib + e * 4 + 1][d];
            v4.z = T[ib + e * 4 + 2][d];
            v4.w = T[ib + e * 4 + 3][d];
            *(float4*)&dst[e * 4] = v4;
        }
    }
}

// ============================================================================
// Kernel 6: final projection + bias. Block 128p x 128o, 256 threads.
// ============================================================================
__global__ void __launch_bounds__(256) out_kernel(
    const float* __restrict__ wo,
    const float* __restrict__ bo,
    float* __restrict__ out)
{
    __shared__ __align__(16) float Bs[16][132];   // [c][p]
    __shared__ __align__(16) float Ws[16][132];   // [c][o]

    const int tid = threadIdx.x;
    const int tx = tid & 15, ty = tid >> 4;
    const int p0 = blockIdx.x * 128;
    const int o0 = blockIdx.y * 128;

    u64 acc[4][8];
    #pragma unroll
    for (int a = 0; a < 4; a++)
        #pragma unroll
        for (int b = 0; b < 8; b++) acc[a][b] = 0ull;

    for (int kt = 0; kt < 32; kt++) {
        const int c0 = kt * 16;
        #pragma unroll
        for (int q = 0; q < 2; q++) {
            int idx = q * 256 + tid;
            int xr = idx >> 5;
            int xc = (idx & 31) * 4;
            *(float4*)&Bs[xr][xc] = *(const float4*)&g_op[(c0 + xr) * NP + p0 + xc];
            int orow = idx >> 2;
            int cg   = (idx & 3) * 4;
            float4 w = *(const float4*)&wo[(o0 + orow) * 512 + c0 + cg];
            Ws[cg + 0][orow] = w.x;
            Ws[cg + 1][orow] = w.y;
            Ws[cg + 2][orow] = w.z;
            Ws[cg + 3][orow] = w.w;
        }
        __syncthreads();
        #pragma unroll
        for (int kk = 0; kk < 16; kk++) MICRO_STEP(Bs[kk], Ws[kk]);
        __syncthreads();
    }

    // stores: float4 along p for each of 8 o's
    #pragma unroll
    for (int oo = 0; oo < 8; oo++) {
        int o_ = o0 + tx * 8 + oo;
        float b = bo[o_];
        float2 r0 = up2(acc[0][oo]);
        float2 r1 = up2(acc[1][oo]);
        float2 r2 = up2(acc[2][oo]);
        float2 r3 = up2(acc[3][oo]);
        float* dst = &out[o_ * NP + p0 + ty * 8];
        *(float4*)&dst[0] = make_float4(r0.x + b, r0.y + b, r1.x + b, r1.y + b);
        *(float4*)&dst[4] = make_float4(r2.x + b, r2.y + b, r3.x + b, r3.y + b);
    }
}

// ============================================================================
extern "C" void kernel_launch(void* const* d_in, const int* in_sizes, int n_in,
                              void* d_out, int out_size)
{
    const float* x   = (const float*)d_in[0];
    const float* wq  = (const float*)d_in[1];
    const float* wkv = (const float*)d_in[2];
    const float* wo  = (const float*)d_in[3];
    const float* bo  = (const float*)d_in[4];
    float* out = (float*)d_out;

    proj_kernel     <<<dim3(NP / 128, 1536 / 128), 256>>>(x, wq, wkv);
    qk_kernel       <<<dim3(4, 4, NG),             256>>>();
    softmax_kernel  <<<dim3(NG * SEQ / 8),         256>>>();
    pv_kernel       <<<dim3(4, NG),                128>>>();
    transpose_kernel<<<dim3(4, NG),                256>>>();
    out_kernel      <<<dim3(NP / 128, 256 / 128),  256>>>(wo, bo, out);
}